// round 1
// baseline (speedup 1.0000x reference)
#include <cuda_runtime.h>

// Shapes fixed by the problem.
#define BB 16
#define CC 64
#define HH 64
#define WW 64
#define CO 64
#define KT 9   // 3x3 taps

// Scratch (allocation-free rule: __device__ globals).
__device__ float g_nhwc[BB * HH * WW * CC];   // [b][y][x][c]
__device__ float g_wr[KT * CC * CO];          // [tap][c][o]

// ---------------------------------------------------------------------------
// Kernel 1: NCHW -> NHWC transpose of the input (coalesced both sides via smem)
// ---------------------------------------------------------------------------
__global__ void nchw2nhwc_kernel(const float* __restrict__ in) {
    __shared__ float tile[64][65];
    int by = blockIdx.x;            // b*64 + y
    int b = by >> 6, y = by & 63;
    for (int i = threadIdx.x; i < 64 * 64; i += blockDim.x) {
        int c = i >> 6, x = i & 63;
        tile[c][x] = in[(((b * 64 + c) * 64 + y) * 64) + x];   // coalesced over x
    }
    __syncthreads();
    for (int i = threadIdx.x; i < 64 * 64; i += blockDim.x) {
        int x = i >> 6, c = i & 63;
        g_nhwc[(((b * 64 + y) * 64 + x) * 64) + c] = tile[c][x]; // coalesced over c
    }
}

// ---------------------------------------------------------------------------
// Kernel 2: weight (Cout, C, 3, 3) -> [tap][c][o]
// ---------------------------------------------------------------------------
__global__ void wreshape_kernel(const float* __restrict__ w) {
    int i = blockIdx.x * blockDim.x + threadIdx.x;   // i = (k*64 + c)*64 + o
    if (i >= KT * CC * CO) return;
    int o = i & 63;
    int c = (i >> 6) & 63;
    int k = i >> 12;
    g_wr[i] = w[(o * 64 + c) * 9 + k];
}

// ---------------------------------------------------------------------------
// Kernel 3: fused deformable sampling + GEMM.
// CTA = 128 threads handles 32 consecutive pixels (same b,p; q0..q0+31) x 64 outs.
// Thread (tx = tid&15, ty = tid>>4): 4 outs {4tx..4tx+3} x 4 px {ty, ty+8, ty+16, ty+24}.
// ---------------------------------------------------------------------------
__global__ __launch_bounds__(128) void dcn_main_kernel(
    const float* __restrict__ offset,   // (B, 18, H, W)
    const float* __restrict__ mask,     // (B, 9, H, W)
    const float* __restrict__ bias,     // (Cout,)
    float* __restrict__ out)            // (B, Cout, H, W)
{
    __shared__ float w_s[64 * 64];      // [c][o] weight tile for current tap (reused as out tile)
    __shared__ float v_s[32 * 64];      // [px][c] modulated samples for current tap
    __shared__ float s_wt[4][32];       // per-px corner weights (incl. mask & validity)
    __shared__ int   s_idx[4][32];      // per-px corner base offsets (elements) within batch slice

    const int tid = threadIdx.x;
    const int tx = tid & 15;            // out group
    const int ty = tid >> 4;            // px group (0..7)
    const int pid0 = blockIdx.x * 32;   // first pixel of tile
    const int b  = pid0 >> 12;
    const int p  = (pid0 >> 6) & 63;
    const int q0 = pid0 & 63;           // 0 or 32 (Wo=64, tile=32)

    float acc[4][4];
    {
        float b0 = bias[tx * 4 + 0];
        float b1 = bias[tx * 4 + 1];
        float b2 = bias[tx * 4 + 2];
        float b3 = bias[tx * 4 + 3];
        #pragma unroll
        for (int i = 0; i < 4; i++) {
            acc[i][0] = b0; acc[i][1] = b1; acc[i][2] = b2; acc[i][3] = b3;
        }
    }

    const float* off_b = offset + (size_t)b * 18 * 64 * 64;
    const float* msk_b = mask   + (size_t)b * 9 * 64 * 64;
    const float* in_b  = g_nhwc + (size_t)b * 64 * 64 * 64;

    for (int k = 0; k < 9; k++) {
        __syncthreads();   // previous GEMM finished reading w_s / v_s

        // ---- load this tap's weight tile [c][o] (coalesced float4) ----
        {
            const float4* wsrc = (const float4*)(g_wr + k * 4096);
            float4* wdst = (float4*)w_s;
            #pragma unroll
            for (int i = 0; i < 8; i++)
                wdst[tid + i * 128] = wsrc[tid + i * 128];
        }

        // ---- per-pixel tap precompute (32 threads, one per pixel) ----
        if (tid < 32) {
            int px = tid;
            int q = q0 + px;
            float oy = off_b[((2 * k)     * 64 + p) * 64 + q];
            float ox = off_b[((2 * k + 1) * 64 + p) * 64 + q];
            float m  = msk_b[(k * 64 + p) * 64 + q];
            float py  = oy + (float)(p - 1 + (k / 3));
            float pxx = ox + (float)(q - 1 + (k % 3));
            float y0f = floorf(py), x0f = floorf(pxx);
            float wy = py - y0f, wx = pxx - x0f;
            int y0 = (int)y0f, x0 = (int)x0f;
            int y1 = y0 + 1,   x1 = x0 + 1;
            float vy0 = (y0 >= 0 && y0 < 64) ? 1.f : 0.f;
            float vy1 = (y1 >= 0 && y1 < 64) ? 1.f : 0.f;
            float vx0 = (x0 >= 0 && x0 < 64) ? 1.f : 0.f;
            float vx1 = (x1 >= 0 && x1 < 64) ? 1.f : 0.f;
            int y0c = min(max(y0, 0), 63), y1c = min(max(y1, 0), 63);
            int x0c = min(max(x0, 0), 63), x1c = min(max(x1, 0), 63);
            s_wt[0][px] = m * (1.f - wy) * (1.f - wx) * vy0 * vx0;
            s_wt[1][px] = m * (1.f - wy) * wx         * vy0 * vx1;
            s_wt[2][px] = m * wy         * (1.f - wx) * vy1 * vx0;
            s_wt[3][px] = m * wy         * wx         * vy1 * vx1;
            s_idx[0][px] = (y0c * 64 + x0c) * 64;
            s_idx[1][px] = (y0c * 64 + x1c) * 64;
            s_idx[2][px] = (y1c * 64 + x0c) * 64;
            s_idx[3][px] = (y1c * 64 + x1c) * 64;
        }
        __syncthreads();

        // ---- sampling: fill v_s[px][c] (coalesced 256B per corner per half-warp) ----
        {
            const int c4 = tx * 4;
            #pragma unroll
            for (int i = 0; i < 4; i++) {
                int px = ty + i * 8;
                float w0 = s_wt[0][px], w1 = s_wt[1][px];
                float w2 = s_wt[2][px], w3 = s_wt[3][px];
                const float4 v0 = *(const float4*)(in_b + s_idx[0][px] + c4);
                const float4 v1 = *(const float4*)(in_b + s_idx[1][px] + c4);
                const float4 v2 = *(const float4*)(in_b + s_idx[2][px] + c4);
                const float4 v3 = *(const float4*)(in_b + s_idx[3][px] + c4);
                float4 a;
                a.x = w0 * v0.x + w1 * v1.x + w2 * v2.x + w3 * v3.x;
                a.y = w0 * v0.y + w1 * v1.y + w2 * v2.y + w3 * v3.y;
                a.z = w0 * v0.z + w1 * v1.z + w2 * v2.z + w3 * v3.z;
                a.w = w0 * v0.w + w1 * v1.w + w2 * v2.w + w3 * v3.w;
                *(float4*)(v_s + px * 64 + c4) = a;   // conflict-free STS.128
            }
        }
        __syncthreads();

        // ---- GEMM over c: 64 steps x (1 LDS.128 + 4 LDS.32 broadcast + 16 FFMA) ----
        #pragma unroll 8
        for (int c = 0; c < 64; c++) {
            float4 wv = *(const float4*)(w_s + c * 64 + tx * 4);
            float a0 = v_s[(ty     ) * 64 + c];
            float a1 = v_s[(ty +  8) * 64 + c];
            float a2 = v_s[(ty + 16) * 64 + c];
            float a3 = v_s[(ty + 24) * 64 + c];
            acc[0][0] += a0 * wv.x; acc[0][1] += a0 * wv.y; acc[0][2] += a0 * wv.z; acc[0][3] += a0 * wv.w;
            acc[1][0] += a1 * wv.x; acc[1][1] += a1 * wv.y; acc[1][2] += a1 * wv.z; acc[1][3] += a1 * wv.w;
            acc[2][0] += a2 * wv.x; acc[2][1] += a2 * wv.y; acc[2][2] += a2 * wv.z; acc[2][3] += a2 * wv.w;
            acc[3][0] += a3 * wv.x; acc[3][1] += a3 * wv.y; acc[3][2] += a3 * wv.z; acc[3][3] += a3 * wv.w;
        }
    }

    // ---- stage outputs in smem (pad 33 -> conflict-free), then coalesced NCHW store ----
    __syncthreads();
    #pragma unroll
    for (int i = 0; i < 4; i++) {
        int px = ty + i * 8;
        #pragma unroll
        for (int j = 0; j < 4; j++)
            w_s[(tx * 4 + j) * 33 + px] = acc[i][j];
    }
    __syncthreads();

    float* ob = out + (((size_t)b * 64) * 64 + p) * 64 + q0;  // out[b][0][p][q0]
    for (int i = tid; i < 64 * 32; i += 128) {
        int o = i >> 5, px = i & 31;
        ob[(size_t)o * 4096 + px] = w_s[o * 33 + px];         // 128B coalesced per warp
    }
}

// ---------------------------------------------------------------------------
// Entry point
// ---------------------------------------------------------------------------
extern "C" void kernel_launch(void* const* d_in, const int* in_sizes, int n_in,
                              void* d_out, int out_size) {
    const float* x      = (const float*)d_in[0];  // (16,64,64,64)
    const float* offset = (const float*)d_in[1];  // (16,18,64,64)
    const float* mask   = (const float*)d_in[2];  // (16,9,64,64)
    const float* weight = (const float*)d_in[3];  // (64,64,3,3)
    const float* bias   = (const float*)d_in[4];  // (64,)
    float* out = (float*)d_out;

    nchw2nhwc_kernel<<<BB * HH, 256>>>(x);
    wreshape_kernel<<<(KT * CC * CO + 255) / 256, 256>>>(weight);
    dcn_main_kernel<<<(BB * HH * WW) / 32, 128>>>(offset, mask, bias, out);
}

// round 3
// speedup vs baseline: 1.4245x; 1.4245x over previous
#include <cuda_runtime.h>
#include <cuda_bf16.h>
#include <cstdint>

// Shapes fixed by the problem.
#define BB 16
#define CC 64
#define HH 64
#define WW 64
#define CO 64
#define KT 9    // 3x3 taps

// Scratch (__device__ globals: allocation-free rule).
__device__ float g_nhwc[BB * HH * WW * CC];   // [b][y][x][c]
// B fragments pre-packed in mma register order:
// idx4 = (((k*2+term)*4+ks)*4+j)*32 + lane ; uint4 = {nt=2j:(b0,b1), nt=2j+1:(b0,b1)}
__device__ uint4 g_bf[KT * 2 * 4 * 4 * 32];   // 9216 uint4 = 144KB

// ---------------------------------------------------------------------------
// helpers
// ---------------------------------------------------------------------------
__device__ __forceinline__ uint32_t smem_u32(const void* p) {
    uint32_t a;
    asm("{ .reg .u64 t; cvta.to.shared.u64 t, %1; cvt.u32.u64 %0, t; }" : "=r"(a) : "l"(p));
    return a;
}
__device__ __forceinline__ void ldsm4(uint32_t* r, uint32_t addr) {
    asm volatile("ldmatrix.sync.aligned.m8n8.x4.shared.b16 {%0,%1,%2,%3}, [%4];"
                 : "=r"(r[0]), "=r"(r[1]), "=r"(r[2]), "=r"(r[3]) : "r"(addr));
}
__device__ __forceinline__ void mma16816(float* c, const uint32_t* a, uint32_t b0, uint32_t b1) {
    asm volatile("mma.sync.aligned.m16n8k16.row.col.f32.bf16.bf16.f32 "
                 "{%0,%1,%2,%3}, {%4,%5,%6,%7}, {%8,%9}, {%0,%1,%2,%3};"
                 : "+f"(c[0]), "+f"(c[1]), "+f"(c[2]), "+f"(c[3])
                 : "r"(a[0]), "r"(a[1]), "r"(a[2]), "r"(a[3]), "r"(b0), "r"(b1));
}
__device__ __forceinline__ uint32_t pack_bf16(float x, float y) {
    __nv_bfloat162 p = __floats2bfloat162_rn(x, y);   // x -> low half
    return *reinterpret_cast<uint32_t*>(&p);
}

// ---------------------------------------------------------------------------
// Kernel 1: NCHW -> NHWC transpose of the input
// ---------------------------------------------------------------------------
__global__ void nchw2nhwc_kernel(const float* __restrict__ in) {
    __shared__ float tile[64][65];
    int by = blockIdx.x;
    int b = by >> 6, y = by & 63;
    for (int i = threadIdx.x; i < 64 * 64; i += blockDim.x) {
        int c = i >> 6, x = i & 63;
        tile[c][x] = in[(((b * 64 + c) * 64 + y) * 64) + x];
    }
    __syncthreads();
    for (int i = threadIdx.x; i < 64 * 64; i += blockDim.x) {
        int x = i >> 6, c = i & 63;
        g_nhwc[(((b * 64 + y) * 64 + x) * 64) + c] = tile[c][x];
    }
}

// ---------------------------------------------------------------------------
// Kernel 2: weight (Cout, C, 3, 3) -> bf16 hi/lo B fragments in mma reg order
// ---------------------------------------------------------------------------
__global__ void wprep_frag(const float* __restrict__ w) {
    int idx = blockIdx.x * 256 + threadIdx.x;
    if (idx >= KT * 2 * 4 * 4 * 32) return;
    int lane = idx & 31;
    int t = idx >> 5;
    int j = t & 3;  t >>= 2;
    int ks = t & 3; t >>= 2;
    int term = t & 1;
    int k = t >> 1;
    uint32_t r32[4];
    #pragma unroll
    for (int cmp = 0; cmp < 4; cmp++) {
        int nt = j * 2 + (cmp >> 1);
        int r  = cmp & 1;
        int n  = nt * 8 + (lane >> 2);
        int kk = ks * 16 + r * 8 + (lane & 3) * 2;
        float v0 = w[(n * 64 + kk    ) * 9 + k];
        float v1 = w[(n * 64 + kk + 1) * 9 + k];
        float x0 = v0, x1 = v1;
        if (term == 1) {
            x0 = v0 - __bfloat162float(__float2bfloat16(v0));
            x1 = v1 - __bfloat162float(__float2bfloat16(v1));
        }
        r32[cmp] = pack_bf16(x0, x1);
    }
    g_bf[idx] = make_uint4(r32[0], r32[1], r32[2], r32[3]);
}

// ---------------------------------------------------------------------------
// Kernel 3: fused deformable sampling + HMMA split-precision GEMM.
// 128 threads = 4 warps. Tile = 128 px (2 image rows) x 64 outs, K = 9 taps x 64.
// Warp w owns px rows [32w, 32w+32) -> 2 m-tiles of 16, all 8 n-tiles.
// ---------------------------------------------------------------------------
#define A_STRIDE 144   // bytes per A row (72 bf16: pad 64->72 for conflict-free frags)

__global__ __launch_bounds__(128, 3)
void dcn_main_kernel(const float* __restrict__ offset,  // (B,18,H,W)
                     const float* __restrict__ mask,    // (B,9,H,W)
                     const float* __restrict__ bias,    // (Cout,)
                     float* __restrict__ out)           // (B,Cout,H,W)
{
    extern __shared__ __align__(16) char smem[];
    char* A_hi = smem;                       // 128 x 144B = 18432
    char* A_lo = smem + 18432;               // 18432
    uint4* Bsm = (uint4*)(smem + 36864);     // 1024 uint4 = 16384
    __shared__ float s_wt[4][128];
    __shared__ int   s_idx[4][128];

    const int tid  = threadIdx.x;
    const int wid  = tid >> 5;
    const int lane = tid & 31;
    const int tx   = tid & 15;     // c-chunk (c = tx*4)
    const int pg   = tid >> 4;     // px group (0..7), px = pg*16 + i

    const int pid0 = blockIdx.x * 128;
    const int b  = pid0 >> 12;
    const int p0 = (pid0 >> 6) & 63;       // image rows p0, p0+1

    const uint32_t a_hi_u = smem_u32(A_hi);
    const uint32_t a_lo_u = a_hi_u + 18432;

    const float* off_b = offset + (size_t)b * 18 * 4096;
    const float* msk_b = mask   + (size_t)b * 9 * 4096;
    const float* in_b  = g_nhwc + (size_t)b * 262144;

    float acc[2][8][4];
    #pragma unroll
    for (int mi = 0; mi < 2; mi++)
        #pragma unroll
        for (int nt = 0; nt < 8; nt++)
            #pragma unroll
            for (int r = 0; r < 4; r++) acc[mi][nt][r] = 0.f;

    for (int k = 0; k < 9; k++) {
        // ---- copy this tap's B fragments to smem (16KB, linear) ----
        {
            const uint4* src = g_bf + k * 1024;
            #pragma unroll
            for (int r = 0; r < 8; r++) Bsm[tid + r * 128] = src[tid + r * 128];
        }
        // ---- per-pixel tap precompute (one px per thread) ----
        {
            int px = tid;
            int p = p0 + (px >> 6);
            int q = px & 63;
            float oy = off_b[((2 * k)     * 64 + p) * 64 + q];
            float ox = off_b[((2 * k + 1) * 64 + p) * 64 + q];
            float m  = msk_b[(k * 64 + p) * 64 + q];
            float py  = oy + (float)(p - 1 + (k / 3));
            float pxx = ox + (float)(q - 1 + (k % 3));
            float y0f = floorf(py), x0f = floorf(pxx);
            float wy = py - y0f, wx = pxx - x0f;
            int y0 = (int)y0f, x0 = (int)x0f;
            int y1 = y0 + 1,   x1 = x0 + 1;
            float vy0 = (y0 >= 0 && y0 < 64) ? 1.f : 0.f;
            float vy1 = (y1 >= 0 && y1 < 64) ? 1.f : 0.f;
            float vx0 = (x0 >= 0 && x0 < 64) ? 1.f : 0.f;
            float vx1 = (x1 >= 0 && x1 < 64) ? 1.f : 0.f;
            int y0c = min(max(y0, 0), 63), y1c = min(max(y1, 0), 63);
            int x0c = min(max(x0, 0), 63), x1c = min(max(x1, 0), 63);
            s_wt[0][px] = m * (1.f - wy) * (1.f - wx) * vy0 * vx0;
            s_wt[1][px] = m * (1.f - wy) * wx         * vy0 * vx1;
            s_wt[2][px] = m * wy         * (1.f - wx) * vy1 * vx0;
            s_wt[3][px] = m * wy         * wx         * vy1 * vx1;
            s_idx[0][px] = (y0c * 64 + x0c) * 64;
            s_idx[1][px] = (y0c * 64 + x1c) * 64;
            s_idx[2][px] = (y1c * 64 + x0c) * 64;
            s_idx[3][px] = (y1c * 64 + x1c) * 64;
        }
        __syncthreads();

        // ---- sampling: bilinear + mask -> bf16 hi/lo into A tiles ----
        {
            const int c4 = tx * 4;
            #pragma unroll
            for (int i = 0; i < 16; i++) {
                int px = pg * 16 + i;
                float w0 = s_wt[0][px], w1 = s_wt[1][px];
                float w2 = s_wt[2][px], w3 = s_wt[3][px];
                const float4 v0 = *(const float4*)(in_b + s_idx[0][px] + c4);
                const float4 v1 = *(const float4*)(in_b + s_idx[1][px] + c4);
                const float4 v2 = *(const float4*)(in_b + s_idx[2][px] + c4);
                const float4 v3 = *(const float4*)(in_b + s_idx[3][px] + c4);
                float a0 = w0 * v0.x + w1 * v1.x + w2 * v2.x + w3 * v3.x;
                float a1 = w0 * v0.y + w1 * v1.y + w2 * v2.y + w3 * v3.y;
                float a2 = w0 * v0.z + w1 * v1.z + w2 * v2.z + w3 * v3.z;
                float a3 = w0 * v0.w + w1 * v1.w + w2 * v2.w + w3 * v3.w;
                uint32_t h01 = pack_bf16(a0, a1);
                uint32_t h23 = pack_bf16(a2, a3);
                float r0 = a0 - __uint_as_float(h01 << 16);
                float r1 = a1 - __uint_as_float(h01 & 0xFFFF0000u);
                float r2 = a2 - __uint_as_float(h23 << 16);
                float r3 = a3 - __uint_as_float(h23 & 0xFFFF0000u);
                uint32_t l01 = pack_bf16(r0, r1);
                uint32_t l23 = pack_bf16(r2, r3);
                int off = px * A_STRIDE + tx * 8;
                *(uint2*)(A_hi + off) = make_uint2(h01, h23);
                *(uint2*)(A_lo + off) = make_uint2(l01, l23);
            }
        }
        __syncthreads();

        // ---- GEMM: per k-step load A frags (ldmatrix) + B frags (LDS.128), MMA ----
        {
            // ldmatrix lane address components (element row/col within A tile)
            const int mat    = lane >> 3;
            const int row_in = lane & 7;
            const int lrow   = ((mat & 1) << 3) + row_in;   // + mi*16 + wid*32
            const int lcolB  = (mat & 2) << 2;              // 0 or 8 elements
            const uint32_t abase = (uint32_t)(wid * 32 + lrow) * A_STRIDE + (uint32_t)lcolB * 2;

            #pragma unroll
            for (int ks = 0; ks < 4; ks++) {
                uint32_t ah[2][4], al[2][4];
                #pragma unroll
                for (int mi = 0; mi < 2; mi++) {
                    uint32_t addr = abase + (uint32_t)(mi * 16) * A_STRIDE + (uint32_t)(ks * 32);
                    ldsm4(ah[mi], a_hi_u + addr);
                    ldsm4(al[mi], a_lo_u + addr);
                }
                uint4 bh[4], bl[4];
                #pragma unroll
                for (int j = 0; j < 4; j++) {
                    bh[j] = Bsm[((0 * 4 + ks) * 4 + j) * 32 + lane];
                    bl[j] = Bsm[((1 * 4 + ks) * 4 + j) * 32 + lane];
                }
                #pragma unroll
                for (int mi = 0; mi < 2; mi++) {
                    #pragma unroll
                    for (int nt = 0; nt < 8; nt++) {
                        uint32_t bh0 = (nt & 1) ? bh[nt >> 1].z : bh[nt >> 1].x;
                        uint32_t bh1 = (nt & 1) ? bh[nt >> 1].w : bh[nt >> 1].y;
                        uint32_t bl0 = (nt & 1) ? bl[nt >> 1].z : bl[nt >> 1].x;
                        uint32_t bl1 = (nt & 1) ? bl[nt >> 1].w : bl[nt >> 1].y;
                        mma16816(acc[mi][nt], ah[mi], bh0, bh1);   // hi*hi
                        mma16816(acc[mi][nt], ah[mi], bl0, bl1);   // hi*lo
                        mma16816(acc[mi][nt], al[mi], bh0, bh1);   // lo*hi
                    }
                }
            }
        }
        __syncthreads();
    }

    // ---- epilogue: direct STG (NCHW), add bias ----
    #pragma unroll
    for (int mi = 0; mi < 2; mi++) {
        #pragma unroll
        for (int half = 0; half < 2; half++) {
            int px = wid * 32 + mi * 16 + (lane >> 2) + half * 8;
            int p  = p0 + (px >> 6);
            int q  = px & 63;
            size_t base = (((size_t)b * 64) * 64 + p) * 64 + q;
            #pragma unroll
            for (int nt = 0; nt < 8; nt++) {
                int o = nt * 8 + (lane & 3) * 2;
                out[base + (size_t)o * 4096]       = acc[mi][nt][half * 2 + 0] + __ldg(bias + o);
                out[base + (size_t)(o + 1) * 4096] = acc[mi][nt][half * 2 + 1] + __ldg(bias + o + 1);
            }
        }
    }
}

// ---------------------------------------------------------------------------
// Entry point
// ---------------------------------------------------------------------------
extern "C" void kernel_launch(void* const* d_in, const int* in_sizes, int n_in,
                              void* d_out, int out_size) {
    const float* x      = (const float*)d_in[0];
    const float* offset = (const float*)d_in[1];
    const float* mask   = (const float*)d_in[2];
    const float* weight = (const float*)d_in[3];
    const float* bias   = (const float*)d_in[4];
    float* out = (float*)d_out;

    const int dyn_smem = 18432 * 2 + 16384;  // 53248
    cudaFuncSetAttribute(dcn_main_kernel, cudaFuncAttributeMaxDynamicSharedMemorySize, dyn_smem);

    nchw2nhwc_kernel<<<BB * HH, 256>>>(x);
    wprep_frag<<<(KT * 2 * 4 * 4 * 32 + 255) / 256, 256>>>(weight);
    dcn_main_kernel<<<(BB * HH * WW) / 128, 128, dyn_smem>>>(offset, mask, bias, out);
}

// round 4
// speedup vs baseline: 2.0161x; 1.4153x over previous
#include <cuda_runtime.h>
#include <cuda_bf16.h>
#include <cuda_fp16.h>
#include <cstdint>

// Shapes fixed by the problem.
#define BB 16
#define CC 64
#define HH 64
#define WW 64
#define CO 64
#define KT 9    // 3x3 taps

// Scratch (__device__ globals: allocation-free rule).
__device__ __half g_nhwc_h[BB * HH * WW * CC];   // [b][y][x][c], fp16
// B fragments pre-packed in mma register order:
// idx4 = (((k*2+term)*4+ks)*4+j)*32 + lane ; uint4 = {nt=2j:(b0,b1), nt=2j+1:(b0,b1)}
__device__ uint4 g_bf[KT * 2 * 4 * 4 * 32];      // 9216 uint4 = 144KB

// ---------------------------------------------------------------------------
// helpers
// ---------------------------------------------------------------------------
__device__ __forceinline__ uint32_t smem_u32(const void* p) {
    uint32_t a;
    asm("{ .reg .u64 t; cvta.to.shared.u64 t, %1; cvt.u32.u64 %0, t; }" : "=r"(a) : "l"(p));
    return a;
}
__device__ __forceinline__ void ldsm4(uint32_t* r, uint32_t addr) {
    asm volatile("ldmatrix.sync.aligned.m8n8.x4.shared.b16 {%0,%1,%2,%3}, [%4];"
                 : "=r"(r[0]), "=r"(r[1]), "=r"(r[2]), "=r"(r[3]) : "r"(addr));
}
__device__ __forceinline__ void mma16816(float* c, const uint32_t* a, uint32_t b0, uint32_t b1) {
    asm volatile("mma.sync.aligned.m16n8k16.row.col.f32.bf16.bf16.f32 "
                 "{%0,%1,%2,%3}, {%4,%5,%6,%7}, {%8,%9}, {%0,%1,%2,%3};"
                 : "+f"(c[0]), "+f"(c[1]), "+f"(c[2]), "+f"(c[3])
                 : "r"(a[0]), "r"(a[1]), "r"(a[2]), "r"(a[3]), "r"(b0), "r"(b1));
}
__device__ __forceinline__ uint32_t pack_bf16(float x, float y) {
    __nv_bfloat162 p = __floats2bfloat162_rn(x, y);   // x -> low half
    return *reinterpret_cast<uint32_t*>(&p);
}

// ---------------------------------------------------------------------------
// Kernel 1: NCHW f32 -> NHWC fp16 transpose of the input
// ---------------------------------------------------------------------------
__global__ void nchw2nhwc_kernel(const float* __restrict__ in) {
    __shared__ float tile[64][65];
    int by = blockIdx.x;
    int b = by >> 6, y = by & 63;
    for (int i = threadIdx.x; i < 64 * 64; i += blockDim.x) {
        int c = i >> 6, x = i & 63;
        tile[c][x] = in[(((b * 64 + c) * 64 + y) * 64) + x];
    }
    __syncthreads();
    for (int i = threadIdx.x; i < 64 * 32; i += blockDim.x) {
        int x = i >> 5, cp = i & 31;
        __half2 hh = __floats2half2_rn(tile[2 * cp][x], tile[2 * cp + 1][x]);
        *reinterpret_cast<__half2*>(g_nhwc_h + (((b * 64 + y) * 64 + x) * 64) + 2 * cp) = hh;
    }
}

// ---------------------------------------------------------------------------
// Kernel 2: weight (Cout, C, 3, 3) -> bf16 hi/lo B fragments in mma reg order
// ---------------------------------------------------------------------------
__global__ void wprep_frag(const float* __restrict__ w) {
    int idx = blockIdx.x * 256 + threadIdx.x;
    if (idx >= KT * 2 * 4 * 4 * 32) return;
    int lane = idx & 31;
    int t = idx >> 5;
    int j = t & 3;  t >>= 2;
    int ks = t & 3; t >>= 2;
    int term = t & 1;
    int k = t >> 1;
    uint32_t r32[4];
    #pragma unroll
    for (int cmp = 0; cmp < 4; cmp++) {
        int nt = j * 2 + (cmp >> 1);
        int r  = cmp & 1;
        int n  = nt * 8 + (lane >> 2);
        int kk = ks * 16 + r * 8 + (lane & 3) * 2;
        float v0 = w[(n * 64 + kk    ) * 9 + k];
        float v1 = w[(n * 64 + kk + 1) * 9 + k];
        float x0 = v0, x1 = v1;
        if (term == 1) {
            x0 = v0 - __bfloat162float(__float2bfloat16(v0));
            x1 = v1 - __bfloat162float(__float2bfloat16(v1));
        }
        r32[cmp] = pack_bf16(x0, x1);
    }
    g_bf[idx] = make_uint4(r32[0], r32[1], r32[2], r32[3]);
}

// ---------------------------------------------------------------------------
// Kernel 3: fused deformable sampling (fp16 gather) + HMMA split bf16 GEMM.
// 128 threads = 4 warps. Tile = 128 px (2 image rows) x 64 outs, K = 9x64.
// Warp w owns px [32w, 32w+32): precompute lane-local, exchange via shuffle.
// ---------------------------------------------------------------------------
#define A_STRIDE 144   // bytes per A row (72 bf16: pad 64->72, conflict-free ldmatrix)

__global__ __launch_bounds__(128, 3)
void dcn_main_kernel(const float* __restrict__ offset,  // (B,18,H,W)
                     const float* __restrict__ mask,    // (B,9,H,W)
                     const float* __restrict__ bias,    // (Cout,)
                     float* __restrict__ out)           // (B,Cout,H,W)
{
    extern __shared__ __align__(16) char smem[];
    char* A_hi = smem;                       // 128 x 144B = 18432
    char* A_lo = smem + 18432;               // 18432
    uint4* Bsm = (uint4*)(smem + 36864);     // 1024 uint4 = 16384

    const int tid  = threadIdx.x;
    const int wid  = tid >> 5;
    const int lane = tid & 31;
    const int tx   = lane & 15;    // c-chunk (c = tx*4)
    const int h    = lane >> 4;    // half-warp: px = wid*32 + h*16 + i

    const int pid0 = blockIdx.x * 128;
    const int b  = pid0 >> 12;
    const int p0 = (pid0 >> 6) & 63;         // image rows p0, p0+1

    const uint32_t a_hi_u = smem_u32(A_hi);
    const uint32_t a_lo_u = a_hi_u + 18432;

    const float*  off_b = offset   + (size_t)b * 18 * 4096;
    const float*  msk_b = mask     + (size_t)b * 9 * 4096;
    const __half* in_b  = g_nhwc_h + (size_t)b * 262144;

    float acc[2][8][4];
    #pragma unroll
    for (int mi = 0; mi < 2; mi++)
        #pragma unroll
        for (int nt = 0; nt < 8; nt++)
            #pragma unroll
            for (int r = 0; r < 4; r++) acc[mi][nt][r] = 0.f;

    for (int k = 0; k < 9; k++) {
        // ---- copy this tap's B fragments to smem (16KB, linear) ----
        {
            const uint4* src = g_bf + k * 1024;
            #pragma unroll
            for (int r = 0; r < 8; r++) Bsm[tid + r * 128] = src[tid + r * 128];
        }
        // ---- per-pixel tap precompute: lane-local px = wid*32 + lane ----
        float mw0, mw1, mw2, mw3;
        int   mi0, mi1, mi2, mi3;
        {
            int px = wid * 32 + lane;
            int p = p0 + (px >> 6);
            int q = px & 63;
            float oy = off_b[((2 * k)     * 64 + p) * 64 + q];
            float ox = off_b[((2 * k + 1) * 64 + p) * 64 + q];
            float m  = msk_b[(k * 64 + p) * 64 + q];
            float py  = oy + (float)(p - 1 + (k / 3));
            float pxx = ox + (float)(q - 1 + (k % 3));
            float y0f = floorf(py), x0f = floorf(pxx);
            float wy = py - y0f, wx = pxx - x0f;
            int y0 = (int)y0f, x0 = (int)x0f;
            int y1 = y0 + 1,   x1 = x0 + 1;
            float vy0 = (y0 >= 0 && y0 < 64) ? 1.f : 0.f;
            float vy1 = (y1 >= 0 && y1 < 64) ? 1.f : 0.f;
            float vx0 = (x0 >= 0 && x0 < 64) ? 1.f : 0.f;
            float vx1 = (x1 >= 0 && x1 < 64) ? 1.f : 0.f;
            int y0c = min(max(y0, 0), 63), y1c = min(max(y1, 0), 63);
            int x0c = min(max(x0, 0), 63), x1c = min(max(x1, 0), 63);
            mw0 = m * (1.f - wy) * (1.f - wx) * vy0 * vx0;
            mw1 = m * (1.f - wy) * wx         * vy0 * vx1;
            mw2 = m * wy         * (1.f - wx) * vy1 * vx0;
            mw3 = m * wy         * wx         * vy1 * vx1;
            mi0 = (y0c * 64 + x0c) * 64;
            mi1 = (y0c * 64 + x1c) * 64;
            mi2 = (y1c * 64 + x0c) * 64;
            mi3 = (y1c * 64 + x1c) * 64;
        }

        // ---- sampling: fp16 bilinear gather -> bf16 hi/lo into A tiles ----
        {
            const int c4 = tx * 4;
            #pragma unroll
            for (int i = 0; i < 16; i++) {
                int sl = h * 16 + i;
                float w0 = __shfl_sync(0xffffffffu, mw0, sl);
                float w1 = __shfl_sync(0xffffffffu, mw1, sl);
                float w2 = __shfl_sync(0xffffffffu, mw2, sl);
                float w3 = __shfl_sync(0xffffffffu, mw3, sl);
                int   i0 = __shfl_sync(0xffffffffu, mi0, sl);
                int   i1 = __shfl_sync(0xffffffffu, mi1, sl);
                int   i2 = __shfl_sync(0xffffffffu, mi2, sl);
                int   i3 = __shfl_sync(0xffffffffu, mi3, sl);
                uint2 u0 = *(const uint2*)(in_b + i0 + c4);
                uint2 u1 = *(const uint2*)(in_b + i1 + c4);
                uint2 u2 = *(const uint2*)(in_b + i2 + c4);
                uint2 u3 = *(const uint2*)(in_b + i3 + c4);
                float2 c0a = __half22float2(*reinterpret_cast<__half2*>(&u0.x));
                float2 c0b = __half22float2(*reinterpret_cast<__half2*>(&u0.y));
                float2 c1a = __half22float2(*reinterpret_cast<__half2*>(&u1.x));
                float2 c1b = __half22float2(*reinterpret_cast<__half2*>(&u1.y));
                float2 c2a = __half22float2(*reinterpret_cast<__half2*>(&u2.x));
                float2 c2b = __half22float2(*reinterpret_cast<__half2*>(&u2.y));
                float2 c3a = __half22float2(*reinterpret_cast<__half2*>(&u3.x));
                float2 c3b = __half22float2(*reinterpret_cast<__half2*>(&u3.y));
                float a0 = w0 * c0a.x + w1 * c1a.x + w2 * c2a.x + w3 * c3a.x;
                float a1 = w0 * c0a.y + w1 * c1a.y + w2 * c2a.y + w3 * c3a.y;
                float a2 = w0 * c0b.x + w1 * c1b.x + w2 * c2b.x + w3 * c3b.x;
                float a3 = w0 * c0b.y + w1 * c1b.y + w2 * c2b.y + w3 * c3b.y;
                uint32_t h01 = pack_bf16(a0, a1);
                uint32_t h23 = pack_bf16(a2, a3);
                float r0 = a0 - __uint_as_float(h01 << 16);
                float r1 = a1 - __uint_as_float(h01 & 0xFFFF0000u);
                float r2 = a2 - __uint_as_float(h23 << 16);
                float r3 = a3 - __uint_as_float(h23 & 0xFFFF0000u);
                uint32_t l01 = pack_bf16(r0, r1);
                uint32_t l23 = pack_bf16(r2, r3);
                int px = wid * 32 + sl;
                int off = px * A_STRIDE + tx * 8;
                *(uint2*)(A_hi + off) = make_uint2(h01, h23);
                *(uint2*)(A_lo + off) = make_uint2(l01, l23);
            }
        }
        __syncthreads();

        // ---- GEMM: per k-step A frags via ldmatrix, B frags via LDS.128 ----
        {
            const int mat    = lane >> 3;
            const int row_in = lane & 7;
            const int lrow   = ((mat & 1) << 3) + row_in;
            const int lcolB  = (mat & 2) << 2;
            const uint32_t abase = (uint32_t)(wid * 32 + lrow) * A_STRIDE + (uint32_t)lcolB * 2;

            #pragma unroll
            for (int ks = 0; ks < 4; ks++) {
                uint32_t ah[2][4], al[2][4];
                #pragma unroll
                for (int mi = 0; mi < 2; mi++) {
                    uint32_t addr = abase + (uint32_t)(mi * 16) * A_STRIDE + (uint32_t)(ks * 32);
                    ldsm4(ah[mi], a_hi_u + addr);
                    ldsm4(al[mi], a_lo_u + addr);
                }
                uint4 bh[4], bl[4];
                #pragma unroll
                for (int j = 0; j < 4; j++) {
                    bh[j] = Bsm[((0 * 4 + ks) * 4 + j) * 32 + lane];
                    bl[j] = Bsm[((1 * 4 + ks) * 4 + j) * 32 + lane];
                }
                #pragma unroll
                for (int mi = 0; mi < 2; mi++) {
                    #pragma unroll
                    for (int nt = 0; nt < 8; nt++) {
                        uint32_t bh0 = (nt & 1) ? bh[nt >> 1].z : bh[nt >> 1].x;
                        uint32_t bh1 = (nt & 1) ? bh[nt >> 1].w : bh[nt >> 1].y;
                        uint32_t bl0 = (nt & 1) ? bl[nt >> 1].z : bl[nt >> 1].x;
                        uint32_t bl1 = (nt & 1) ? bl[nt >> 1].w : bl[nt >> 1].y;
                        mma16816(acc[mi][nt], ah[mi], bh0, bh1);   // hi*hi
                        mma16816(acc[mi][nt], ah[mi], bl0, bl1);   // hi*lo
                        mma16816(acc[mi][nt], al[mi], bh0, bh1);   // lo*hi
                    }
                }
            }
        }
        __syncthreads();
    }

    // ---- epilogue: direct STG (NCHW), add bias ----
    #pragma unroll
    for (int mi = 0; mi < 2; mi++) {
        #pragma unroll
        for (int half = 0; half < 2; half++) {
            int px = wid * 32 + mi * 16 + (lane >> 2) + half * 8;
            int p  = p0 + (px >> 6);
            int q  = px & 63;
            size_t base = (((size_t)b * 64) * 64 + p) * 64 + q;
            #pragma unroll
            for (int nt = 0; nt < 8; nt++) {
                int o = nt * 8 + (lane & 3) * 2;
                out[base + (size_t)o * 4096]       = acc[mi][nt][half * 2 + 0] + __ldg(bias + o);
                out[base + (size_t)(o + 1) * 4096] = acc[mi][nt][half * 2 + 1] + __ldg(bias + o + 1);
            }
        }
    }
}

// ---------------------------------------------------------------------------
// Entry point
// ---------------------------------------------------------------------------
extern "C" void kernel_launch(void* const* d_in, const int* in_sizes, int n_in,
                              void* d_out, int out_size) {
    const float* x      = (const float*)d_in[0];
    const float* offset = (const float*)d_in[1];
    const float* mask   = (const float*)d_in[2];
    const float* weight = (const float*)d_in[3];
    const float* bias   = (const float*)d_in[4];
    float* out = (float*)d_out;

    const int dyn_smem = 18432 * 2 + 16384;  // 53248
    cudaFuncSetAttribute(dcn_main_kernel, cudaFuncAttributeMaxDynamicSharedMemorySize, dyn_smem);

    nchw2nhwc_kernel<<<BB * HH, 256>>>(x);
    wprep_frag<<<(KT * 2 * 4 * 4 * 32 + 255) / 256, 256>>>(weight);
    dcn_main_kernel<<<(BB * HH * WW) / 128, 128, dyn_smem>>>(offset, mask, bias, out);
}

// round 5
// speedup vs baseline: 2.5649x; 1.2722x over previous
#include <cuda_runtime.h>
#include <cuda_fp16.h>
#include <cstdint>

// Shapes fixed by the problem.
#define BB 16
#define CC 64
#define HH 64
#define WW 64
#define CO 64
#define KT 9    // 3x3 taps

// Scratch (__device__ globals: allocation-free rule).
__device__ __half g_nhwc_h[BB * HH * WW * CC];   // [b][y][x][c], fp16
// B fragments (fp16 hi/lo) pre-packed in mma register order:
// idx4 = (((k*2+term)*4+ks)*4+j)*32 + lane ; uint4 = {nt=2j:(b0,b1), nt=2j+1:(b0,b1)}
__device__ uint4 g_bf[KT * 2 * 4 * 4 * 32];      // 9216 uint4 = 144KB

// ---------------------------------------------------------------------------
// helpers
// ---------------------------------------------------------------------------
__device__ __forceinline__ uint32_t smem_u32(const void* p) {
    uint32_t a;
    asm("{ .reg .u64 t; cvta.to.shared.u64 t, %1; cvt.u32.u64 %0, t; }" : "=r"(a) : "l"(p));
    return a;
}
__device__ __forceinline__ void ldsm4(uint32_t* r, uint32_t addr) {
    asm volatile("ldmatrix.sync.aligned.m8n8.x4.shared.b16 {%0,%1,%2,%3}, [%4];"
                 : "=r"(r[0]), "=r"(r[1]), "=r"(r[2]), "=r"(r[3]) : "r"(addr));
}
__device__ __forceinline__ void mma16816h(float* c, const uint32_t* a, uint32_t b0, uint32_t b1) {
    asm volatile("mma.sync.aligned.m16n8k16.row.col.f32.f16.f16.f32 "
                 "{%0,%1,%2,%3}, {%4,%5,%6,%7}, {%8,%9}, {%0,%1,%2,%3};"
                 : "+f"(c[0]), "+f"(c[1]), "+f"(c[2]), "+f"(c[3])
                 : "r"(a[0]), "r"(a[1]), "r"(a[2]), "r"(a[3]), "r"(b0), "r"(b1));
}
__device__ __forceinline__ uint32_t pack_half(float x, float y) {
    __half2 p = __floats2half2_rn(x, y);   // x -> low half
    return *reinterpret_cast<uint32_t*>(&p);
}

// ---------------------------------------------------------------------------
// Kernel 1: NCHW f32 -> NHWC fp16 transpose of the input
// ---------------------------------------------------------------------------
__global__ void nchw2nhwc_kernel(const float* __restrict__ in) {
    __shared__ float tile[64][65];
    int by = blockIdx.x;
    int b = by >> 6, y = by & 63;
    #pragma unroll
    for (int i = threadIdx.x; i < 64 * 64; i += 256) {
        int c = i >> 6, x = i & 63;
        tile[c][x] = in[(((b * 64 + c) * 64 + y) * 64) + x];
    }
    __syncthreads();
    #pragma unroll
    for (int i = threadIdx.x; i < 64 * 32; i += 256) {
        int x = i >> 5, cp = i & 31;
        __half2 hh = __floats2half2_rn(tile[2 * cp][x], tile[2 * cp + 1][x]);
        *reinterpret_cast<__half2*>(g_nhwc_h + (((b * 64 + y) * 64 + x) * 64) + 2 * cp) = hh;
    }
}

// ---------------------------------------------------------------------------
// Kernel 2: weight (Cout, C, 3, 3) -> fp16 hi/lo B fragments in mma reg order
// ---------------------------------------------------------------------------
__global__ void wprep_frag(const float* __restrict__ w) {
    int idx = blockIdx.x * 256 + threadIdx.x;
    if (idx >= KT * 2 * 4 * 4 * 32) return;
    int lane = idx & 31;
    int t = idx >> 5;
    int j = t & 3;  t >>= 2;
    int ks = t & 3; t >>= 2;
    int term = t & 1;
    int k = t >> 1;
    uint32_t r32[4];
    #pragma unroll
    for (int cmp = 0; cmp < 4; cmp++) {
        int nt = j * 2 + (cmp >> 1);
        int r  = cmp & 1;
        int n  = nt * 8 + (lane >> 2);
        int kk = ks * 16 + r * 8 + (lane & 3) * 2;
        float v0 = w[(n * 64 + kk    ) * 9 + k];
        float v1 = w[(n * 64 + kk + 1) * 9 + k];
        float x0, x1;
        if (term == 0) {
            x0 = v0; x1 = v1;                       // hi = rn(v)
        } else {
            x0 = v0 - __half2float(__float2half_rn(v0));   // lo = v - hi
            x1 = v1 - __half2float(__float2half_rn(v1));
        }
        r32[cmp] = pack_half(x0, x1);
    }
    g_bf[idx] = make_uint4(r32[0], r32[1], r32[2], r32[3]);
}

// ---------------------------------------------------------------------------
// Kernel 3: fused deformable sampling (fp16 gather) + fp16 HMMA (B 2-term split).
// 128 threads = 4 warps. Tile = 128 px (2 image rows) x 64 outs, K = 9x64.
// A is warp-private: only __syncwarp between write and ldmatrix read.
// B double-buffered: 1 CTA barrier per tap.
// ---------------------------------------------------------------------------
#define A_STRIDE 144   // bytes per A row (72 fp16: pad 64->72, conflict-free ldmatrix)

__global__ __launch_bounds__(128, 4)
void dcn_main_kernel(const float* __restrict__ offset,  // (B,18,H,W)
                     const float* __restrict__ mask,    // (B,9,H,W)
                     const float* __restrict__ bias,    // (Cout,)
                     float* __restrict__ out)           // (B,Cout,H,W)
{
    extern __shared__ __align__(16) char smem[];
    char*  A_t  = smem;                        // 128 x 144B = 18432
    uint4* Bsm0 = (uint4*)(smem + 18432);      // 1024 uint4 = 16384 (buffer 0)
    uint4* Bsm1 = Bsm0 + 1024;                 // 16384 (buffer 1)

    const int tid  = threadIdx.x;
    const int wid  = tid >> 5;
    const int lane = tid & 31;
    const int tx   = lane & 15;    // c-chunk (c = tx*4)
    const int h    = lane >> 4;    // half-warp

    const int pid0 = blockIdx.x * 128;
    const int b  = pid0 >> 12;
    const int p0 = (pid0 >> 6) & 63;           // image rows p0, p0+1

    const uint32_t a_u = smem_u32(A_t);

    const float*  off_b = offset   + (size_t)b * 18 * 4096;
    const float*  msk_b = mask     + (size_t)b * 9 * 4096;
    const __half* in_b  = g_nhwc_h + (size_t)b * 262144;

    float acc[2][8][4];
    #pragma unroll
    for (int mi = 0; mi < 2; mi++)
        #pragma unroll
        for (int nt = 0; nt < 8; nt++)
            #pragma unroll
            for (int r = 0; r < 4; r++) acc[mi][nt][r] = 0.f;

    // preload B[0] into buffer 0
    {
        const uint4* src = g_bf;
        #pragma unroll
        for (int r = 0; r < 8; r++) Bsm0[tid + r * 128] = src[tid + r * 128];
    }
    __syncthreads();

    for (int k = 0; k < 9; k++) {
        uint4* Bcur = (k & 1) ? Bsm1 : Bsm0;
        uint4* Bnxt = (k & 1) ? Bsm0 : Bsm1;

        // ---- prefetch next tap's B fragments (read next tap, barrier-protected) ----
        if (k < 8) {
            const uint4* src = g_bf + (k + 1) * 1024;
            #pragma unroll
            for (int r = 0; r < 8; r++) Bnxt[tid + r * 128] = src[tid + r * 128];
        }

        // ---- per-pixel tap precompute: lane-local px = wid*32 + lane ----
        float mw0, mw1, mw2, mw3;
        int   mi0, mi1, mi2, mi3;
        {
            int px = wid * 32 + lane;
            int p = p0 + (px >> 6);
            int q = px & 63;
            float oy = off_b[((2 * k)     * 64 + p) * 64 + q];
            float ox = off_b[((2 * k + 1) * 64 + p) * 64 + q];
            float m  = msk_b[(k * 64 + p) * 64 + q];
            float py  = oy + (float)(p - 1 + (k / 3));
            float pxx = ox + (float)(q - 1 + (k % 3));
            float y0f = floorf(py), x0f = floorf(pxx);
            float wy = py - y0f, wx = pxx - x0f;
            int y0 = (int)y0f, x0 = (int)x0f;
            int y1 = y0 + 1,   x1 = x0 + 1;
            float vy0 = (y0 >= 0 && y0 < 64) ? 1.f : 0.f;
            float vy1 = (y1 >= 0 && y1 < 64) ? 1.f : 0.f;
            float vx0 = (x0 >= 0 && x0 < 64) ? 1.f : 0.f;
            float vx1 = (x1 >= 0 && x1 < 64) ? 1.f : 0.f;
            int y0c = min(max(y0, 0), 63), y1c = min(max(y1, 0), 63);
            int x0c = min(max(x0, 0), 63), x1c = min(max(x1, 0), 63);
            mw0 = m * (1.f - wy) * (1.f - wx) * vy0 * vx0;
            mw1 = m * (1.f - wy) * wx         * vy0 * vx1;
            mw2 = m * wy         * (1.f - wx) * vy1 * vx0;
            mw3 = m * wy         * wx         * vy1 * vx1;
            mi0 = (y0c * 64 + x0c) * 64;
            mi1 = (y0c * 64 + x1c) * 64;
            mi2 = (y1c * 64 + x0c) * 64;
            mi3 = (y1c * 64 + x1c) * 64;
        }

        // ---- sampling: fp16 bilinear gather -> fp16 A tile (warp-private rows) ----
        {
            const int c4 = tx * 4;
            #pragma unroll
            for (int i = 0; i < 16; i++) {
                int sl = h * 16 + i;
                float w0 = __shfl_sync(0xffffffffu, mw0, sl);
                float w1 = __shfl_sync(0xffffffffu, mw1, sl);
                float w2 = __shfl_sync(0xffffffffu, mw2, sl);
                float w3 = __shfl_sync(0xffffffffu, mw3, sl);
                int   i0 = __shfl_sync(0xffffffffu, mi0, sl);
                int   i1 = __shfl_sync(0xffffffffu, mi1, sl);
                int   i2 = __shfl_sync(0xffffffffu, mi2, sl);
                int   i3 = __shfl_sync(0xffffffffu, mi3, sl);
                uint2 u0 = *(const uint2*)(in_b + i0 + c4);
                uint2 u1 = *(const uint2*)(in_b + i1 + c4);
                uint2 u2 = *(const uint2*)(in_b + i2 + c4);
                uint2 u3 = *(const uint2*)(in_b + i3 + c4);
                float2 c0a = __half22float2(*reinterpret_cast<__half2*>(&u0.x));
                float2 c0b = __half22float2(*reinterpret_cast<__half2*>(&u0.y));
                float2 c1a = __half22float2(*reinterpret_cast<__half2*>(&u1.x));
                float2 c1b = __half22float2(*reinterpret_cast<__half2*>(&u1.y));
                float2 c2a = __half22float2(*reinterpret_cast<__half2*>(&u2.x));
                float2 c2b = __half22float2(*reinterpret_cast<__half2*>(&u2.y));
                float2 c3a = __half22float2(*reinterpret_cast<__half2*>(&u3.x));
                float2 c3b = __half22float2(*reinterpret_cast<__half2*>(&u3.y));
                float a0 = w0 * c0a.x + w1 * c1a.x + w2 * c2a.x + w3 * c3a.x;
                float a1 = w0 * c0a.y + w1 * c1a.y + w2 * c2a.y + w3 * c3a.y;
                float a2 = w0 * c0b.x + w1 * c1b.x + w2 * c2b.x + w3 * c3b.x;
                float a3 = w0 * c0b.y + w1 * c1b.y + w2 * c2b.y + w3 * c3b.y;
                int px = wid * 32 + sl;
                int off = px * A_STRIDE + tx * 8;
                *(uint2*)(A_t + off) = make_uint2(pack_half(a0, a1), pack_half(a2, a3));
            }
        }
        __syncwarp();   // A rows are warp-private; order STS -> LDSM within warp

        // ---- GEMM: per k-step A frags via ldmatrix, B hi/lo frags via LDS.128 ----
        {
            const int mat    = lane >> 3;
            const int row_in = lane & 7;
            const int lrow   = ((mat & 1) << 3) + row_in;
            const int lcolB  = (mat & 2) << 2;
            const uint32_t abase = (uint32_t)(wid * 32 + lrow) * A_STRIDE + (uint32_t)lcolB * 2;

            #pragma unroll
            for (int ks = 0; ks < 4; ks++) {
                uint32_t ah[2][4];
                #pragma unroll
                for (int mi = 0; mi < 2; mi++) {
                    uint32_t addr = abase + (uint32_t)(mi * 16) * A_STRIDE + (uint32_t)(ks * 32);
                    ldsm4(ah[mi], a_u + addr);
                }
                uint4 bh[4], bl[4];
                #pragma unroll
                for (int j = 0; j < 4; j++) {
                    bh[j] = Bcur[((0 * 4 + ks) * 4 + j) * 32 + lane];
                    bl[j] = Bcur[((1 * 4 + ks) * 4 + j) * 32 + lane];
                }
                #pragma unroll
                for (int mi = 0; mi < 2; mi++) {
                    #pragma unroll
                    for (int nt = 0; nt < 8; nt++) {
                        uint32_t bh0 = (nt & 1) ? bh[nt >> 1].z : bh[nt >> 1].x;
                        uint32_t bh1 = (nt & 1) ? bh[nt >> 1].w : bh[nt >> 1].y;
                        uint32_t bl0 = (nt & 1) ? bl[nt >> 1].z : bl[nt >> 1].x;
                        uint32_t bl1 = (nt & 1) ? bl[nt >> 1].w : bl[nt >> 1].y;
                        mma16816h(acc[mi][nt], ah[mi], bh0, bh1);   // A * B_hi
                        mma16816h(acc[mi][nt], ah[mi], bl0, bl1);   // A * B_lo
                    }
                }
            }
        }
        __syncthreads();   // B buffers: all reads of Bcur done; Bnxt fully written
    }

    // ---- epilogue: direct STG (NCHW), add bias ----
    #pragma unroll
    for (int mi = 0; mi < 2; mi++) {
        #pragma unroll
        for (int half = 0; half < 2; half++) {
            int px = wid * 32 + mi * 16 + (lane >> 2) + half * 8;
            int p  = p0 + (px >> 6);
            int q  = px & 63;
            size_t base = (((size_t)b * 64) * 64 + p) * 64 + q;
            #pragma unroll
            for (int nt = 0; nt < 8; nt++) {
                int o = nt * 8 + (lane & 3) * 2;
                out[base + (size_t)o * 4096]       = acc[mi][nt][half * 2 + 0] + __ldg(bias + o);
                out[base + (size_t)(o + 1) * 4096] = acc[mi][nt][half * 2 + 1] + __ldg(bias + o + 1);
            }
        }
    }
}

// ---------------------------------------------------------------------------
// Entry point
// ---------------------------------------------------------------------------
extern "C" void kernel_launch(void* const* d_in, const int* in_sizes, int n_in,
                              void* d_out, int out_size) {
    const float* x      = (const float*)d_in[0];
    const float* offset = (const float*)d_in[1];
    const float* mask   = (const float*)d_in[2];
    const float* weight = (const float*)d_in[3];
    const float* bias   = (const float*)d_in[4];
    float* out = (float*)d_out;

    const int dyn_smem = 18432 + 2 * 16384;  // 51200
    cudaFuncSetAttribute(dcn_main_kernel, cudaFuncAttributeMaxDynamicSharedMemorySize, dyn_smem);

    nchw2nhwc_kernel<<<BB * HH, 256>>>(x);
    wprep_frag<<<(KT * 2 * 4 * 4 * 32 + 255) / 256, 256>>>(weight);
    dcn_main_kernel<<<(BB * HH * WW) / 128, 128, dyn_smem>>>(offset, mask, bias, out);
}

// round 6
// speedup vs baseline: 2.9374x; 1.1453x over previous
#include <cuda_runtime.h>
#include <cuda_fp16.h>
#include <cstdint>

// Shapes fixed by the problem.
#define BB 16
#define CC 64
#define HH 64
#define WW 64
#define CO 64
#define KT 9    // 3x3 taps

// Scratch (__device__ globals: allocation-free rule).
__device__ __half g_nhwc_h[BB * HH * WW * CC];   // [b][y][x][c], fp16
// B fragments (fp16 hi/lo) pre-packed in mma register order:
// idx4 = (((k*2+term)*4+ks)*4+j)*32 + lane ; uint4 = {nt=2j:(b0,b1), nt=2j+1:(b0,b1)}
__device__ uint4 g_bf[KT * 2 * 4 * 4 * 32];      // 9216 uint4 = 144KB

// ---------------------------------------------------------------------------
// helpers
// ---------------------------------------------------------------------------
__device__ __forceinline__ uint32_t smem_u32(const void* p) {
    uint32_t a;
    asm("{ .reg .u64 t; cvta.to.shared.u64 t, %1; cvt.u32.u64 %0, t; }" : "=r"(a) : "l"(p));
    return a;
}
__device__ __forceinline__ void ldsm4(uint32_t* r, uint32_t addr) {
    asm volatile("ldmatrix.sync.aligned.m8n8.x4.shared.b16 {%0,%1,%2,%3}, [%4];"
                 : "=r"(r[0]), "=r"(r[1]), "=r"(r[2]), "=r"(r[3]) : "r"(addr));
}
__device__ __forceinline__ void mma16816h(float* c, const uint32_t* a, uint32_t b0, uint32_t b1) {
    asm volatile("mma.sync.aligned.m16n8k16.row.col.f32.f16.f16.f32 "
                 "{%0,%1,%2,%3}, {%4,%5,%6,%7}, {%8,%9}, {%0,%1,%2,%3};"
                 : "+f"(c[0]), "+f"(c[1]), "+f"(c[2]), "+f"(c[3])
                 : "r"(a[0]), "r"(a[1]), "r"(a[2]), "r"(a[3]), "r"(b0), "r"(b1));
}
__device__ __forceinline__ uint32_t pack_half(float x, float y) {
    __half2 p = __floats2half2_rn(x, y);   // x -> low half
    return *reinterpret_cast<uint32_t*>(&p);
}
__device__ __forceinline__ __half2 u2h2(uint32_t u) {
    return *reinterpret_cast<__half2*>(&u);
}

// ---------------------------------------------------------------------------
// Kernel 1: NCHW f32 -> NHWC fp16 transpose of the input
// ---------------------------------------------------------------------------
__global__ void nchw2nhwc_kernel(const float* __restrict__ in) {
    __shared__ float tile[64][65];
    int by = blockIdx.x;
    int b = by >> 6, y = by & 63;
    #pragma unroll
    for (int i = threadIdx.x; i < 64 * 16; i += 256) {     // float4 loads
        int c = i >> 4, x4 = (i & 15) * 4;
        float4 v = *(const float4*)(in + (((b * 64 + c) * 64 + y) * 64) + x4);
        tile[c][x4 + 0] = v.x; tile[c][x4 + 1] = v.y;
        tile[c][x4 + 2] = v.z; tile[c][x4 + 3] = v.w;
    }
    __syncthreads();
    #pragma unroll
    for (int i = threadIdx.x; i < 64 * 32; i += 256) {
        int x = i >> 5, cp = i & 31;
        __half2 hh = __floats2half2_rn(tile[2 * cp][x], tile[2 * cp + 1][x]);
        *reinterpret_cast<__half2*>(g_nhwc_h + (((b * 64 + y) * 64 + x) * 64) + 2 * cp) = hh;
    }
}

// ---------------------------------------------------------------------------
// Kernel 2: weight (Cout, C, 3, 3) -> fp16 hi/lo B fragments in mma reg order
// ---------------------------------------------------------------------------
__global__ void wprep_frag(const float* __restrict__ w) {
    int idx = blockIdx.x * 256 + threadIdx.x;
    if (idx >= KT * 2 * 4 * 4 * 32) return;
    int lane = idx & 31;
    int t = idx >> 5;
    int j = t & 3;  t >>= 2;
    int ks = t & 3; t >>= 2;
    int term = t & 1;
    int k = t >> 1;
    uint32_t r32[4];
    #pragma unroll
    for (int cmp = 0; cmp < 4; cmp++) {
        int nt = j * 2 + (cmp >> 1);
        int r  = cmp & 1;
        int n  = nt * 8 + (lane >> 2);
        int kk = ks * 16 + r * 8 + (lane & 3) * 2;
        float v0 = w[(n * 64 + kk    ) * 9 + k];
        float v1 = w[(n * 64 + kk + 1) * 9 + k];
        float x0, x1;
        if (term == 0) {
            x0 = v0; x1 = v1;                              // hi = rn(v)
        } else {
            x0 = v0 - __half2float(__float2half_rn(v0));   // lo = v - hi
            x1 = v1 - __half2float(__float2half_rn(v1));
        }
        r32[cmp] = pack_half(x0, x1);
    }
    g_bf[idx] = make_uint4(r32[0], r32[1], r32[2], r32[3]);
}

// ---------------------------------------------------------------------------
// Kernel 3: fused deformable sampling (HFMA2) + fp16 HMMA (B 2-term split).
// 128 threads = 4 warps, NO CTA barriers in main loop:
//   A-tile is warp-private (syncwarp only); B frags read directly from global
//   (L1-resident: 16KB/tap shared across all warps & CTAs).
// ---------------------------------------------------------------------------
#define A_STRIDE 144   // bytes per A row (72 fp16: pad 64->72, conflict-free ldmatrix)

__global__ __launch_bounds__(128, 4)
void dcn_main_kernel(const float* __restrict__ offset,  // (B,18,H,W)
                     const float* __restrict__ mask,    // (B,9,H,W)
                     const float* __restrict__ bias,    // (Cout,)
                     float* __restrict__ out)           // (B,Cout,H,W)
{
    extern __shared__ __align__(16) char smem[];
    char* A_t = smem;                          // 128 x 144B = 18432

    const int tid  = threadIdx.x;
    const int wid  = tid >> 5;
    const int lane = tid & 31;
    const int tx   = lane & 15;    // c-chunk (c = tx*4)
    const int h    = lane >> 4;    // half-warp

    const int pid0 = blockIdx.x * 128;
    const int b  = pid0 >> 12;
    const int p0 = (pid0 >> 6) & 63;           // image rows p0, p0+1

    const uint32_t a_u = smem_u32(A_t);

    const float*  off_b = offset   + (size_t)b * 18 * 4096;
    const float*  msk_b = mask     + (size_t)b * 9 * 4096;
    const __half* in_b  = g_nhwc_h + (size_t)b * 262144;

    float acc[2][8][4];
    #pragma unroll
    for (int mi = 0; mi < 2; mi++)
        #pragma unroll
        for (int nt = 0; nt < 8; nt++)
            #pragma unroll
            for (int r = 0; r < 4; r++) acc[mi][nt][r] = 0.f;

    for (int k = 0; k < 9; k++) {
        // ---- per-pixel tap precompute: lane-local px = wid*32 + lane ----
        uint32_t wABu, wCDu;
        int mi0, mi1, mi2, mi3;
        {
            int px = wid * 32 + lane;
            int p = p0 + (px >> 6);
            int q = px & 63;
            float oy = off_b[((2 * k)     * 64 + p) * 64 + q];
            float ox = off_b[((2 * k + 1) * 64 + p) * 64 + q];
            float m  = msk_b[(k * 64 + p) * 64 + q];
            float py  = oy + (float)(p - 1 + (k / 3));
            float pxx = ox + (float)(q - 1 + (k % 3));
            float y0f = floorf(py), x0f = floorf(pxx);
            float wy = py - y0f, wx = pxx - x0f;
            int y0 = (int)y0f, x0 = (int)x0f;
            int y1 = y0 + 1,   x1 = x0 + 1;
            float vy0 = (y0 >= 0 && y0 < 64) ? 1.f : 0.f;
            float vy1 = (y1 >= 0 && y1 < 64) ? 1.f : 0.f;
            float vx0 = (x0 >= 0 && x0 < 64) ? 1.f : 0.f;
            float vx1 = (x1 >= 0 && x1 < 64) ? 1.f : 0.f;
            int y0c = min(max(y0, 0), 63), y1c = min(max(y1, 0), 63);
            int x0c = min(max(x0, 0), 63), x1c = min(max(x1, 0), 63);
            float w0 = m * (1.f - wy) * (1.f - wx) * vy0 * vx0;
            float w1 = m * (1.f - wy) * wx         * vy0 * vx1;
            float w2 = m * wy         * (1.f - wx) * vy1 * vx0;
            float w3 = m * wy         * wx         * vy1 * vx1;
            wABu = pack_half(w0, w1);
            wCDu = pack_half(w2, w3);
            mi0 = (y0c * 64 + x0c) * 64;
            mi1 = (y0c * 64 + x1c) * 64;
            mi2 = (y1c * 64 + x0c) * 64;
            mi3 = (y1c * 64 + x1c) * 64;
        }

        // ---- sampling: fp16 bilinear (HFMA2) -> fp16 A tile (warp-private) ----
        {
            const int c4 = tx * 4;
            #pragma unroll
            for (int i = 0; i < 16; i++) {
                int sl = h * 16 + i;
                uint32_t wab = __shfl_sync(0xffffffffu, wABu, sl);
                uint32_t wcd = __shfl_sync(0xffffffffu, wCDu, sl);
                int i0 = __shfl_sync(0xffffffffu, mi0, sl);
                int i1 = __shfl_sync(0xffffffffu, mi1, sl);
                int i2 = __shfl_sync(0xffffffffu, mi2, sl);
                int i3 = __shfl_sync(0xffffffffu, mi3, sl);
                __half2 w0 = __low2half2(u2h2(wab));
                __half2 w1 = __high2half2(u2h2(wab));
                __half2 w2 = __low2half2(u2h2(wcd));
                __half2 w3 = __high2half2(u2h2(wcd));
                uint2 u0 = *(const uint2*)(in_b + i0 + c4);
                uint2 u1 = *(const uint2*)(in_b + i1 + c4);
                uint2 u2 = *(const uint2*)(in_b + i2 + c4);
                uint2 u3 = *(const uint2*)(in_b + i3 + c4);
                __half2 ax = __hmul2(w0, u2h2(u0.x));
                ax = __hfma2(w1, u2h2(u1.x), ax);
                ax = __hfma2(w2, u2h2(u2.x), ax);
                ax = __hfma2(w3, u2h2(u3.x), ax);
                __half2 ay = __hmul2(w0, u2h2(u0.y));
                ay = __hfma2(w1, u2h2(u1.y), ay);
                ay = __hfma2(w2, u2h2(u2.y), ay);
                ay = __hfma2(w3, u2h2(u3.y), ay);
                int px = wid * 32 + sl;
                int off = px * A_STRIDE + tx * 8;
                *(uint2*)(A_t + off) = make_uint2(*reinterpret_cast<uint32_t*>(&ax),
                                                  *reinterpret_cast<uint32_t*>(&ay));
            }
        }
        __syncwarp();   // STS -> LDSM (RAW within warp, cross-lane)

        // ---- GEMM: A frags via ldmatrix, B hi/lo frags via LDG (L1-resident) ----
        {
            const int mat    = lane >> 3;
            const int row_in = lane & 7;
            const int lrow   = ((mat & 1) << 3) + row_in;
            const int lcolB  = (mat & 2) << 2;
            const uint32_t abase = (uint32_t)(wid * 32 + lrow) * A_STRIDE + (uint32_t)lcolB * 2;
            const uint4* __restrict__ Bg = g_bf + k * 1024;

            #pragma unroll
            for (int ks = 0; ks < 4; ks++) {
                uint32_t ah[2][4];
                #pragma unroll
                for (int mi = 0; mi < 2; mi++) {
                    uint32_t addr = abase + (uint32_t)(mi * 16) * A_STRIDE + (uint32_t)(ks * 32);
                    ldsm4(ah[mi], a_u + addr);
                }
                #pragma unroll
                for (int j = 0; j < 4; j++) {
                    uint4 bh = __ldg(Bg + ((0 * 4 + ks) * 4 + j) * 32 + lane);
                    uint4 bl = __ldg(Bg + ((1 * 4 + ks) * 4 + j) * 32 + lane);
                    #pragma unroll
                    for (int sub = 0; sub < 2; sub++) {
                        int nt = j * 2 + sub;
                        uint32_t bh0 = sub ? bh.z : bh.x;
                        uint32_t bh1 = sub ? bh.w : bh.y;
                        uint32_t bl0 = sub ? bl.z : bl.x;
                        uint32_t bl1 = sub ? bl.w : bl.y;
                        #pragma unroll
                        for (int mi = 0; mi < 2; mi++) {
                            mma16816h(acc[mi][nt], ah[mi], bh0, bh1);   // A * B_hi
                            mma16816h(acc[mi][nt], ah[mi], bl0, bl1);   // A * B_lo
                        }
                    }
                }
            }
        }
        __syncwarp();   // LDSM (tap k) -> STS (tap k+1): WAR within warp
    }

    // ---- epilogue: direct STG (NCHW), add bias ----
    #pragma unroll
    for (int mi = 0; mi < 2; mi++) {
        #pragma unroll
        for (int half = 0; half < 2; half++) {
            int px = wid * 32 + mi * 16 + (lane >> 2) + half * 8;
            int p  = p0 + (px >> 6);
            int q  = px & 63;
            size_t base = (((size_t)b * 64) * 64 + p) * 64 + q;
            #pragma unroll
            for (int nt = 0; nt < 8; nt++) {
                int o = nt * 8 + (lane & 3) * 2;
                out[base + (size_t)o * 4096]       = acc[mi][nt][half * 2 + 0] + __ldg(bias + o);
                out[base + (size_t)(o + 1) * 4096] = acc[mi][nt][half * 2 + 1] + __ldg(bias + o + 1);
            }
        }
    }
}

// ---------------------------------------------------------------------------
// Entry point
// ---------------------------------------------------------------------------
extern "C" void kernel_launch(void* const* d_in, const int* in_sizes, int n_in,
                              void* d_out, int out_size) {
    const float* x      = (const float*)d_in[0];
    const float* offset = (const float*)d_in[1];
    const float* mask   = (const float*)d_in[2];
    const float* weight = (const float*)d_in[3];
    const float* bias   = (const float*)d_in[4];
    float* out = (float*)d_out;

    const int dyn_smem = 18432;
    cudaFuncSetAttribute(dcn_main_kernel, cudaFuncAttributeMaxDynamicSharedMemorySize, dyn_smem);

    nchw2nhwc_kernel<<<BB * HH, 256>>>(x);
    wprep_frag<<<(KT * 2 * 4 * 4 * 32 + 255) / 256, 256>>>(weight);
    dcn_main_kernel<<<(BB * HH * WW) / 128, 128, dyn_smem>>>(offset, mask, bias, out);
}

// round 7
// speedup vs baseline: 3.6950x; 1.2579x over previous
#include <cuda_runtime.h>
#include <cuda_fp16.h>
#include <cstdint>

// Shapes fixed by the problem.
#define BB 16
#define CC 64
#define HH 64
#define WW 64
#define CO 64
#define KT 9    // 3x3 taps

// Scratch (__device__ globals: allocation-free rule).
__device__ __half g_nhwc_h[BB * HH * WW * CC];   // [b][y][x][c], fp16
// B fragments (fp16, single term) pre-packed in mma register order:
// idx4 = ((k*4+ks)*4+j)*32 + lane ; uint4 = {nt=2j:(b0,b1), nt=2j+1:(b0,b1)}
__device__ uint4 g_bf[KT * 4 * 4 * 32];          // 4608 uint4 = 72KB

// ---------------------------------------------------------------------------
// helpers
// ---------------------------------------------------------------------------
__device__ __forceinline__ uint32_t smem_u32(const void* p) {
    uint32_t a;
    asm("{ .reg .u64 t; cvta.to.shared.u64 t, %1; cvt.u32.u64 %0, t; }" : "=r"(a) : "l"(p));
    return a;
}
__device__ __forceinline__ void ldsm4(uint32_t* r, uint32_t addr) {
    asm volatile("ldmatrix.sync.aligned.m8n8.x4.shared.b16 {%0,%1,%2,%3}, [%4];"
                 : "=r"(r[0]), "=r"(r[1]), "=r"(r[2]), "=r"(r[3]) : "r"(addr));
}
__device__ __forceinline__ void mma16816h(float* c, const uint32_t* a, uint32_t b0, uint32_t b1) {
    asm volatile("mma.sync.aligned.m16n8k16.row.col.f32.f16.f16.f32 "
                 "{%0,%1,%2,%3}, {%4,%5,%6,%7}, {%8,%9}, {%0,%1,%2,%3};"
                 : "+f"(c[0]), "+f"(c[1]), "+f"(c[2]), "+f"(c[3])
                 : "r"(a[0]), "r"(a[1]), "r"(a[2]), "r"(a[3]), "r"(b0), "r"(b1));
}
__device__ __forceinline__ uint32_t pack_half(float x, float y) {
    __half2 p = __floats2half2_rn(x, y);   // x -> low half
    return *reinterpret_cast<uint32_t*>(&p);
}
__device__ __forceinline__ __half2 u2h2(uint32_t u) {
    return *reinterpret_cast<__half2*>(&u);
}

// ---------------------------------------------------------------------------
// Kernel 1 (merged): blocks [0,1024): NCHW f32 -> NHWC fp16 transpose
//                    blocks [1024,1042): weight -> fp16 B fragments (reg order)
// ---------------------------------------------------------------------------
__global__ void prep_kernel(const float* __restrict__ in, const float* __restrict__ w) {
    if (blockIdx.x < 1024) {
        __shared__ float tile[64][65];
        int by = blockIdx.x;
        int b = by >> 6, y = by & 63;
        #pragma unroll
        for (int i = threadIdx.x; i < 64 * 16; i += 256) {     // float4 loads
            int c = i >> 4, x4 = (i & 15) * 4;
            float4 v = *(const float4*)(in + (((b * 64 + c) * 64 + y) * 64) + x4);
            tile[c][x4 + 0] = v.x; tile[c][x4 + 1] = v.y;
            tile[c][x4 + 2] = v.z; tile[c][x4 + 3] = v.w;
        }
        __syncthreads();
        #pragma unroll
        for (int i = threadIdx.x; i < 64 * 16; i += 256) {     // uint2 stores
            int x = i >> 4, cq = i & 15;
            int c0 = cq * 4;
            uint2 o;
            o.x = pack_half(tile[c0][x],     tile[c0 + 1][x]);
            o.y = pack_half(tile[c0 + 2][x], tile[c0 + 3][x]);
            *reinterpret_cast<uint2*>(g_nhwc_h + (((b * 64 + y) * 64 + x) * 64) + c0) = o;
        }
    } else {
        int idx = (blockIdx.x - 1024) * 256 + threadIdx.x;     // 18 blocks: 4608
        if (idx >= KT * 4 * 4 * 32) return;
        int lane = idx & 31;
        int t = idx >> 5;
        int j  = t & 3;
        int ks = (t >> 2) & 3;
        int k  = t >> 4;
        uint32_t r32[4];
        #pragma unroll
        for (int cmp = 0; cmp < 4; cmp++) {
            int nt = j * 2 + (cmp >> 1);
            int r  = cmp & 1;
            int n  = nt * 8 + (lane >> 2);
            int kk = ks * 16 + r * 8 + (lane & 3) * 2;
            float v0 = w[(n * 64 + kk    ) * 9 + k];
            float v1 = w[(n * 64 + kk + 1) * 9 + k];
            r32[cmp] = pack_half(v0, v1);
        }
        g_bf[idx] = make_uint4(r32[0], r32[1], r32[2], r32[3]);
    }
}

// ---------------------------------------------------------------------------
// Kernel 2: fused deformable sampling (HFMA2) + fp16 HMMA.
// 128 threads = 4 warps, no CTA barriers in main loop:
//   A-tile warp-private (syncwarp only); B frags via LDG (L1-resident, 8KB/tap).
// ---------------------------------------------------------------------------
#define A_STRIDE 144   // bytes per A row (72 fp16: pad 64->72, conflict-free ldmatrix)

__global__ __launch_bounds__(128, 4)
void dcn_main_kernel(const float* __restrict__ offset,  // (B,18,H,W)
                     const float* __restrict__ mask,    // (B,9,H,W)
                     const float* __restrict__ bias,    // (Cout,)
                     float* __restrict__ out)           // (B,Cout,H,W)
{
    extern __shared__ __align__(16) char smem[];
    char* A_t = smem;                          // 128 x 144B = 18432

    const int tid  = threadIdx.x;
    const int wid  = tid >> 5;
    const int lane = tid & 31;
    const int tx   = lane & 15;    // c-chunk (c = tx*4)
    const int h    = lane >> 4;    // half-warp

    const int pid0 = blockIdx.x * 128;
    const int b  = pid0 >> 12;
    const int p0 = (pid0 >> 6) & 63;           // image rows p0, p0+1

    const uint32_t a_u = smem_u32(A_t);

    const float*  off_b = offset   + (size_t)b * 18 * 4096;
    const float*  msk_b = mask     + (size_t)b * 9 * 4096;
    const __half* in_b  = g_nhwc_h + (size_t)b * 262144;

    float acc[2][8][4];
    #pragma unroll
    for (int mi = 0; mi < 2; mi++)
        #pragma unroll
        for (int nt = 0; nt < 8; nt++)
            #pragma unroll
            for (int r = 0; r < 4; r++) acc[mi][nt][r] = 0.f;

    for (int k = 0; k < 9; k++) {
        // ---- per-pixel tap precompute: lane-local px = wid*32 + lane ----
        uint32_t wABu, wCDu, pk01, pk23;   // packed weights + packed corner coords
        {
            int px = wid * 32 + lane;
            int p = p0 + (px >> 6);
            int q = px & 63;
            float oy = off_b[((2 * k)     * 64 + p) * 64 + q];
            float ox = off_b[((2 * k + 1) * 64 + p) * 64 + q];
            float m  = msk_b[(k * 64 + p) * 64 + q];
            float py  = oy + (float)(p - 1 + (k / 3));
            float pxx = ox + (float)(q - 1 + (k % 3));
            float y0f = floorf(py), x0f = floorf(pxx);
            float wy = py - y0f, wx = pxx - x0f;
            int y0 = (int)y0f, x0 = (int)x0f;
            int y1 = y0 + 1,   x1 = x0 + 1;
            float vy0 = (y0 >= 0 && y0 < 64) ? 1.f : 0.f;
            float vy1 = (y1 >= 0 && y1 < 64) ? 1.f : 0.f;
            float vx0 = (x0 >= 0 && x0 < 64) ? 1.f : 0.f;
            float vx1 = (x1 >= 0 && x1 < 64) ? 1.f : 0.f;
            int y0c = min(max(y0, 0), 63), y1c = min(max(y1, 0), 63);
            int x0c = min(max(x0, 0), 63), x1c = min(max(x1, 0), 63);
            float w0 = m * (1.f - wy) * (1.f - wx) * vy0 * vx0;
            float w1 = m * (1.f - wy) * wx         * vy0 * vx1;
            float w2 = m * wy         * (1.f - wx) * vy1 * vx0;
            float w3 = m * wy         * wx         * vy1 * vx1;
            wABu = pack_half(w0, w1);
            wCDu = pack_half(w2, w3);
            pk01 = (uint32_t)(y0c * 64 + x0c) | ((uint32_t)(y0c * 64 + x1c) << 16);
            pk23 = (uint32_t)(y1c * 64 + x0c) | ((uint32_t)(y1c * 64 + x1c) << 16);
        }

        // ---- sampling: fp16 bilinear (HFMA2) -> fp16 A tile (warp-private) ----
        {
            const int c4 = tx * 4;
            #pragma unroll
            for (int i = 0; i < 16; i++) {
                int sl = h * 16 + i;
                uint32_t wab = __shfl_sync(0xffffffffu, wABu, sl);
                uint32_t wcd = __shfl_sync(0xffffffffu, wCDu, sl);
                uint32_t p01 = __shfl_sync(0xffffffffu, pk01, sl);
                uint32_t p23 = __shfl_sync(0xffffffffu, pk23, sl);
                int i0 = (int)(p01 & 0xFFFFu) << 6;
                int i1 = (int)(p01 >> 16) << 6;
                int i2 = (int)(p23 & 0xFFFFu) << 6;
                int i3 = (int)(p23 >> 16) << 6;
                __half2 w0 = __low2half2(u2h2(wab));
                __half2 w1 = __high2half2(u2h2(wab));
                __half2 w2 = __low2half2(u2h2(wcd));
                __half2 w3 = __high2half2(u2h2(wcd));
                uint2 u0 = *(const uint2*)(in_b + i0 + c4);
                uint2 u1 = *(const uint2*)(in_b + i1 + c4);
                uint2 u2 = *(const uint2*)(in_b + i2 + c4);
                uint2 u3 = *(const uint2*)(in_b + i3 + c4);
                __half2 ax = __hmul2(w0, u2h2(u0.x));
                ax = __hfma2(w1, u2h2(u1.x), ax);
                ax = __hfma2(w2, u2h2(u2.x), ax);
                ax = __hfma2(w3, u2h2(u3.x), ax);
                __half2 ay = __hmul2(w0, u2h2(u0.y));
                ay = __hfma2(w1, u2h2(u1.y), ay);
                ay = __hfma2(w2, u2h2(u2.y), ay);
                ay = __hfma2(w3, u2h2(u3.y), ay);
                int px = wid * 32 + sl;
                int off = px * A_STRIDE + tx * 8;
                *(uint2*)(A_t + off) = make_uint2(*reinterpret_cast<uint32_t*>(&ax),
                                                  *reinterpret_cast<uint32_t*>(&ay));
            }
        }
        __syncwarp();   // STS -> LDSM (RAW within warp, cross-lane)

        // ---- GEMM: A frags via ldmatrix, B frags via LDG (L1-resident) ----
        {
            const int mat    = lane >> 3;
            const int row_in = lane & 7;
            const int lrow   = ((mat & 1) << 3) + row_in;
            const int lcolB  = (mat & 2) << 2;
            const uint32_t abase = (uint32_t)(wid * 32 + lrow) * A_STRIDE + (uint32_t)lcolB * 2;
            const uint4* __restrict__ Bg = g_bf + k * 512;

            #pragma unroll
            for (int ks = 0; ks < 4; ks++) {
                uint32_t ah[2][4];
                #pragma unroll
                for (int mi = 0; mi < 2; mi++) {
                    uint32_t addr = abase + (uint32_t)(mi * 16) * A_STRIDE + (uint32_t)(ks * 32);
                    ldsm4(ah[mi], a_u + addr);
                }
                #pragma unroll
                for (int j = 0; j < 4; j++) {
                    uint4 bh = __ldg(Bg + (ks * 4 + j) * 32 + lane);
                    #pragma unroll
                    for (int sub = 0; sub < 2; sub++) {
                        int nt = j * 2 + sub;
                        uint32_t b0 = sub ? bh.z : bh.x;
                        uint32_t b1 = sub ? bh.w : bh.y;
                        mma16816h(acc[0][nt], ah[0], b0, b1);
                        mma16816h(acc[1][nt], ah[1], b0, b1);
                    }
                }
            }
        }
        __syncwarp();   // LDSM (tap k) -> STS (tap k+1): WAR within warp
    }

    // ---- epilogue: stage 32 o-planes at a time in smem, coalesced float4 STG ----
    float* osm = (float*)A_t;                  // 32 x 132 f32 = 16896B <= 18432
    #pragma unroll
    for (int chunk = 0; chunk < 2; chunk++) {
        __syncthreads();   // previous chunk's reads done (and tap-9 A reads done)
        #pragma unroll
        for (int mi = 0; mi < 2; mi++) {
            #pragma unroll
            for (int half = 0; half < 2; half++) {
                int px = wid * 32 + mi * 16 + (lane >> 2) + half * 8;
                #pragma unroll
                for (int jj = 0; jj < 4; jj++) {           // nt within chunk
                    int nt = chunk * 4 + jj;
                    int o  = nt * 8 + (lane & 3) * 2;
                    osm[(o & 31) * 132 + px]       = acc[mi][nt][half * 2 + 0] + __ldg(bias + o);
                    osm[((o + 1) & 31) * 132 + px] = acc[mi][nt][half * 2 + 1] + __ldg(bias + o + 1);
                }
            }
        }
        __syncthreads();
        // store: 32 o-planes x 128 px; out[b][o][p0][0..63],[p0+1][0..63] contiguous 512B
        float* ob = out + (((size_t)b * 64 + chunk * 32) * 64 + p0) * 64;
        #pragma unroll
        for (int r = 0; r < 8; r++) {
            int i  = tid + r * 128;            // i in [0,1024): o32 = i>>5, px4 = (i&31)*4
            int o32 = i >> 5, px4 = (i & 31) * 4;
            float4 v = make_float4(osm[o32 * 132 + px4],     osm[o32 * 132 + px4 + 1],
                                   osm[o32 * 132 + px4 + 2], osm[o32 * 132 + px4 + 3]);
            *(float4*)(ob + (size_t)o32 * 4096 + px4) = v;
        }
    }
}

// ---------------------------------------------------------------------------
// Entry point
// ---------------------------------------------------------------------------
extern "C" void kernel_launch(void* const* d_in, const int* in_sizes, int n_in,
                              void* d_out, int out_size) {
    const float* x      = (const float*)d_in[0];
    const float* offset = (const float*)d_in[1];
    const float* mask   = (const float*)d_in[2];
    const float* weight = (const float*)d_in[3];
    const float* bias   = (const float*)d_in[4];
    float* out = (float*)d_out;

    const int dyn_smem = 18432;
    cudaFuncSetAttribute(dcn_main_kernel, cudaFuncAttributeMaxDynamicSharedMemorySize, dyn_smem);

    prep_kernel<<<1024 + 18, 256>>>(x, weight);
    dcn_main_kernel<<<(BB * HH * WW) / 128, 128, dyn_smem>>>(offset, mask, bias, out);
}